// round 16
// baseline (speedup 1.0000x reference)
#include <cuda_runtime.h>
#include <cstdint>

// Local covariance: out = boxmean5( (center(x)-boxmean5(x)) * (center(y)-boxmean5(y)) )
// x,y: [16,1,1024,1024] f32 -> out: [16,1,1016,1016] f32
//
// R15 = R14 (packed f32x2 math, register rings + shuffles, per-warp depth-8
// cp.async SMEM ring, no warmup gate) with grid reshaped to 720 blocks
// (ORS 52) + 5 blocks/SM cap: packed live state (~72 regs) now fits the
// 102-reg budget, so occupancy rises ~25% where R8's unpacked attempt spilled.

#define H  1024
#define W  1024
#define OH 1016
#define OW 1016
#define NB 16

#define CPWARP 120            // valid output cols per warp (128 raw - 8 halo)
#define NCS    9              // ceil(1016/120)
#define ORS    52             // output rows per strip
#define IRS    60             // input rows per strip (= ORS + 8, multiple of 5)
#define NRS    20             // 20*52 = 1040 >= 1016
#define DEPTH  8              // cp.async pipeline depth (rows in flight)

typedef unsigned long long u64;

__device__ __forceinline__ u64 pk2(float lo, float hi)
{ u64 r; asm("mov.b64 %0, {%1, %2};" : "=l"(r) : "f"(lo), "f"(hi)); return r; }

__device__ __forceinline__ void upk2(float& lo, float& hi, u64 p)
{ asm("mov.b64 {%0, %1}, %2;" : "=f"(lo), "=f"(hi) : "l"(p)); }

__device__ __forceinline__ u64 addx2(u64 a, u64 b)
{ u64 d; asm("add.rn.f32x2 %0, %1, %2;" : "=l"(d) : "l"(a), "l"(b)); return d; }

__device__ __forceinline__ u64 mulx2(u64 a, u64 b)
{ u64 d; asm("mul.rn.f32x2 %0, %1, %2;" : "=l"(d) : "l"(a), "l"(b)); return d; }

__device__ __forceinline__ u64 fmax2(u64 a, u64 b, u64 c)
{ u64 d; asm("fma.rn.f32x2 %0, %1, %2, %3;" : "=l"(d) : "l"(a), "l"(b), "l"(c)); return d; }

__device__ __forceinline__ void cp16(uint32_t dst, const void* src, uint32_t zf)
{
    // 16-byte async copy; zf==0 -> zero-fill (no global read)
    asm volatile("cp.async.cg.shared.global [%0], [%1], 16, %2;\n"
                 :: "r"(dst), "l"(src), "r"(zf) : "memory");
}

__global__ __launch_bounds__(128, 5)
void cov_kernel(const float* __restrict__ x,
                const float* __restrict__ y,
                float* __restrict__ out)
{
    // per-warp ring: DEPTH stages x (32 lanes x 16B x + 32 lanes x 16B y) = 1KB/stage
    __shared__ __align__(16) float4 ring[4][DEPTH][64];

    const int lane = threadIdx.x & 31;
    const int wrp  = threadIdx.x >> 5;

    const int cs = blockIdx.x;               // column strip 0..8
    const int rs = blockIdx.y * 4 + wrp;     // row strip 0..19
    const int b  = blockIdx.z;

    const int c0 = cs * CPWARP + lane * 4;   // first raw col of lane
    const int r0 = rs * ORS;                 // first input row of strip

    const float* __restrict__ xb = x + (long)b * (H * W);
    const float* __restrict__ yb = y + (long)b * (H * W);
    float*       __restrict__ ob = out + (long)b * (OH * OW);

    const bool colok = (c0 < W);
    const int  cc    = colok ? c0 : 0;                 // clamped col (address safety)
    const bool outok = (lane < 30) && (c0 < OW);
    const float inv25 = 1.0f / 25.0f;

    const uint32_t zfc = colok ? 16u : 0u;
    const uint32_t sb  = (uint32_t)__cvta_generic_to_shared(&ring[wrp][0][0]);
    const uint32_t sll = lane * 16;

    // ---- prime pipeline: rows r0 .. r0+DEPTH-1 into stages 0..DEPTH-1 ----
    #pragma unroll
    for (int d = 0; d < DEPTH; ++d) {
        const int row = r0 + d;
        const int rL  = row < H ? row : (H - 1);
        const uint32_t zf = (row < H) ? zfc : 0u;
        const uint32_t dst = sb + ((uint32_t)d << 10) + sll;
        cp16(dst,       xb + (long)rL * W + cc, zf);
        cp16(dst + 512, yb + (long)rL * W + cc, zf);
        asm volatile("cp.async.commit_group;" ::: "memory");
    }

    // packed state: each u64 = (x-quantity, y-quantity)
    u64 xyr[5][4];      // raw-row ring, (x,y) per col
    u64 vsP[4];         // vertical running 5-sums (vsx, vsy)
    u64 hprP[5][2];     // hp ring: (hp0,hp1),(hp2,hp3)
    u64 vhpP[2];        // vertical running 5-sum of hp
    #pragma unroll
    for (int s = 0; s < 5; ++s) {
        #pragma unroll
        for (int i = 0; i < 4; ++i) xyr[s][i] = 0ull;
        hprP[s][0] = 0ull; hprP[s][1] = 0ull;
    }
    #pragma unroll
    for (int i = 0; i < 4; ++i) vsP[i] = 0ull;
    vhpP[0] = 0ull; vhpP[1] = 0ull;

    const u64 neg1P   = pk2(-1.f, -1.f);
    const u64 ninv25P = pk2(-inv25, -inv25);
    const u64 inv25P  = pk2(inv25, inv25);

    for (int rr = 0; rr < IRS; rr += 5) {
        #pragma unroll
        for (int ph = 0; ph < 5; ++ph) {
            const int rrp = rr + ph;
            const int st  = rrp & (DEPTH - 1);

            // ---- wait for row rrp's copies, consume ----
            asm volatile("cp.async.wait_group 7;" ::: "memory");
            float4 xv = ring[wrp][st][lane];
            float4 yv = ring[wrp][st][32 + lane];

            // ---- refill same stage with row rrp+DEPTH ----
            {
                const int row = r0 + rrp + DEPTH;
                const int rL  = row < H ? row : (H - 1);
                const uint32_t zf = ((rrp + DEPTH) < IRS && row < H) ? zfc : 0u;
                const uint32_t dst = sb + ((uint32_t)st << 10) + sll;
                cp16(dst,       xb + (long)rL * W + cc, zf);
                cp16(dst + 512, yb + (long)rL * W + cc, zf);
                asm volatile("cp.async.commit_group;" ::: "memory");
            }

            // ---- pack new row, vertical running 5-sums (packed) ----
            u64 xyn[4];
            xyn[0] = pk2(xv.x, yv.x); xyn[1] = pk2(xv.y, yv.y);
            xyn[2] = pk2(xv.z, yv.z); xyn[3] = pk2(xv.w, yv.w);
            #pragma unroll
            for (int i = 0; i < 4; ++i) {
                vsP[i] = addx2(vsP[i], fmax2(xyr[ph][i], neg1P, xyn[i]));
                xyr[ph][i] = xyn[i];
            }

            // ---- neighbor (lane+1) vertical sums via half-shuffles ----
            u64 nP[4];
            #pragma unroll
            for (int i = 0; i < 4; ++i) {
                float lo, hi;
                upk2(lo, hi, vsP[i]);
                nP[i] = pk2(__shfl_down_sync(0xffffffffu, lo, 1),
                            __shfl_down_sync(0xffffffffu, hi, 1));
            }

            // ---- horizontal 5-sums -> 5x5 box sums (packed sliding chain) ----
            u64 bP[4];
            {
                u64 t = addx2(addx2(vsP[0], vsP[1]), addx2(vsP[2], vsP[3]));
                bP[0] = addx2(t, nP[0]);
                bP[1] = addx2(fmax2(vsP[0], neg1P, bP[0]), nP[1]);
                bP[2] = addx2(fmax2(vsP[1], neg1P, bP[1]), nP[2]);
                bP[3] = addx2(fmax2(vsP[2], neg1P, bP[2]), nP[3]);
            }

            // ---- center pixels: row rrp-2 (ring slot (ph+3)%5), col u+2 ----
            const int sc = (ph + 3) % 5;
            u64 cP[4];
            cP[0] = xyr[sc][2];
            cP[1] = xyr[sc][3];
            {
                float l0, h0, l1, h1;
                upk2(l0, h0, xyr[sc][0]);
                upk2(l1, h1, xyr[sc][1]);
                cP[2] = pk2(__shfl_down_sync(0xffffffffu, l0, 1),
                            __shfl_down_sync(0xffffffffu, h0, 1));
                cP[3] = pk2(__shfl_down_sync(0xffffffffu, l1, 1),
                            __shfl_down_sync(0xffffffffu, h1, 1));
            }

            // ---- pc = (cx - bx/25) * (cy - by/25) ----
            float pc[4];
            #pragma unroll
            for (int i = 0; i < 4; ++i) {
                u64 t = fmax2(bP[i], ninv25P, cP[i]);
                float lo, hi;
                upk2(lo, hi, t);
                pc[i] = lo * hi;
            }

            // ---- horizontal 5-sum of p (scalar chain; NO warmup gate:
            //      early garbage values cancel exactly via the hp ring) ----
            float np[4];
            #pragma unroll
            for (int i = 0; i < 4; ++i)
                np[i] = __shfl_down_sync(0xffffffffu, pc[i], 1);

            float hp0, hp1, hp2, hp3;
            {
                float t = (pc[0] + pc[1]) + (pc[2] + pc[3]);
                hp0 = t + np[0];
                hp1 = hp0 - pc[0] + np[1];
                hp2 = hp1 - pc[1] + np[2];
                hp3 = hp2 - pc[2] + np[3];
            }

            // ---- vertical running 5-sum of hp (packed) ----
            u64 hp01 = pk2(hp0, hp1);
            u64 hp23 = pk2(hp2, hp3);
            vhpP[0] = addx2(vhpP[0], fmax2(hprP[ph][0], neg1P, hp01)); hprP[ph][0] = hp01;
            vhpP[1] = addx2(vhpP[1], fmax2(hprP[ph][1], neg1P, hp23)); hprP[ph][1] = hp23;

            if (rrp >= 8) {
                const int orow = r0 + rrp - 8;
                if (outok && orow < OH) {
                    u64 o01 = mulx2(vhpP[0], inv25P);
                    u64 o23 = mulx2(vhpP[1], inv25P);
                    float o0, o1, o2, o3;
                    upk2(o0, o1, o01);
                    upk2(o2, o3, o23);
                    __stcs((float4*)(ob + (long)orow * OW + c0),
                           make_float4(o0, o1, o2, o3));
                }
            }
        }
    }
}

extern "C" void kernel_launch(void* const* d_in, const int* in_sizes, int n_in,
                              void* d_out, int out_size)
{
    (void)in_sizes; (void)n_in; (void)out_size;
    const float* x = (const float*)d_in[0];
    const float* y = (const float*)d_in[1];
    float* out = (float*)d_out;

    dim3 grid(NCS, NRS / 4, NB);   // 9 col strips x 20 row strips x 16 images
    cov_kernel<<<grid, 128>>>(x, y, out);
}

// round 17
// speedup vs baseline: 1.1096x; 1.1096x over previous
#include <cuda_runtime.h>
#include <cstdint>

// Local covariance: out = boxmean5( (center(x)-boxmean5(x)) * (center(y)-boxmean5(y)) )
// x,y: [16,1,1024,1024] f32 -> out: [16,1,1016,1016] f32
//
// R17 = R14 (best: packed f32x2 math, register rings + shuffles, per-warp
// depth-8 cp.async SMEM ring, 576 blocks, 4 blocks/SM) with the two serial
// sliding-sum chains (box sums bP, horizontal p-sums hp) restructured as
// depth-3 balanced trees via shared partials: ~40 cy less dependent latency
// per row for +4 ops, targeting the exposed-latency gap at 4 warps/SMSP.

#define H  1024
#define W  1024
#define OH 1016
#define OW 1016
#define NB 16

#define CPWARP 120            // valid output cols per warp (128 raw - 8 halo)
#define NCS    9              // ceil(1016/120)
#define ORS    67             // output rows per strip
#define IRS    75             // input rows per strip (= ORS + 8, multiple of 5)
#define NRS    16             // 16*67 = 1072 >= 1016
#define DEPTH  8              // cp.async pipeline depth (rows in flight)

typedef unsigned long long u64;

__device__ __forceinline__ u64 pk2(float lo, float hi)
{ u64 r; asm("mov.b64 %0, {%1, %2};" : "=l"(r) : "f"(lo), "f"(hi)); return r; }

__device__ __forceinline__ void upk2(float& lo, float& hi, u64 p)
{ asm("mov.b64 {%0, %1}, %2;" : "=f"(lo), "=f"(hi) : "l"(p)); }

__device__ __forceinline__ u64 addx2(u64 a, u64 b)
{ u64 d; asm("add.rn.f32x2 %0, %1, %2;" : "=l"(d) : "l"(a), "l"(b)); return d; }

__device__ __forceinline__ u64 mulx2(u64 a, u64 b)
{ u64 d; asm("mul.rn.f32x2 %0, %1, %2;" : "=l"(d) : "l"(a), "l"(b)); return d; }

__device__ __forceinline__ u64 fmax2(u64 a, u64 b, u64 c)
{ u64 d; asm("fma.rn.f32x2 %0, %1, %2, %3;" : "=l"(d) : "l"(a), "l"(b), "l"(c)); return d; }

__device__ __forceinline__ void cp16(uint32_t dst, const void* src, uint32_t zf)
{
    // 16-byte async copy; zf==0 -> zero-fill (no global read)
    asm volatile("cp.async.cg.shared.global [%0], [%1], 16, %2;\n"
                 :: "r"(dst), "l"(src), "r"(zf) : "memory");
}

__global__ __launch_bounds__(128, 4)
void cov_kernel(const float* __restrict__ x,
                const float* __restrict__ y,
                float* __restrict__ out)
{
    // per-warp ring: DEPTH stages x (32 lanes x 16B x + 32 lanes x 16B y) = 1KB/stage
    __shared__ __align__(16) float4 ring[4][DEPTH][64];

    const int lane = threadIdx.x & 31;
    const int wrp  = threadIdx.x >> 5;

    const int cs = blockIdx.x;               // column strip 0..8
    const int rs = blockIdx.y * 4 + wrp;     // row strip 0..15
    const int b  = blockIdx.z;

    const int c0 = cs * CPWARP + lane * 4;   // first raw col of lane
    const int r0 = rs * ORS;                 // first input row of strip

    const float* __restrict__ xb = x + (long)b * (H * W);
    const float* __restrict__ yb = y + (long)b * (H * W);
    float*       __restrict__ ob = out + (long)b * (OH * OW);

    const bool colok = (c0 < W);
    const int  cc    = colok ? c0 : 0;                 // clamped col (address safety)
    const bool outok = (lane < 30) && (c0 < OW);
    const float inv25 = 1.0f / 25.0f;

    const uint32_t zfc = colok ? 16u : 0u;
    const uint32_t sb  = (uint32_t)__cvta_generic_to_shared(&ring[wrp][0][0]);
    const uint32_t sll = lane * 16;

    // ---- prime pipeline: rows r0 .. r0+DEPTH-1 into stages 0..DEPTH-1 ----
    #pragma unroll
    for (int d = 0; d < DEPTH; ++d) {
        const int row = r0 + d;
        const int rL  = row < H ? row : (H - 1);
        const uint32_t zf = (row < H) ? zfc : 0u;
        const uint32_t dst = sb + ((uint32_t)d << 10) + sll;
        cp16(dst,       xb + (long)rL * W + cc, zf);
        cp16(dst + 512, yb + (long)rL * W + cc, zf);
        asm volatile("cp.async.commit_group;" ::: "memory");
    }

    // packed state: each u64 = (x-quantity, y-quantity)
    u64 xyr[5][4];      // raw-row ring, (x,y) per col
    u64 vsP[4];         // vertical running 5-sums (vsx, vsy)
    u64 hprP[5][2];     // hp ring: (hp0,hp1),(hp2,hp3)
    u64 vhpP[2];        // vertical running 5-sum of hp
    #pragma unroll
    for (int s = 0; s < 5; ++s) {
        #pragma unroll
        for (int i = 0; i < 4; ++i) xyr[s][i] = 0ull;
        hprP[s][0] = 0ull; hprP[s][1] = 0ull;
    }
    #pragma unroll
    for (int i = 0; i < 4; ++i) vsP[i] = 0ull;
    vhpP[0] = 0ull; vhpP[1] = 0ull;

    const u64 neg1P   = pk2(-1.f, -1.f);
    const u64 ninv25P = pk2(-inv25, -inv25);
    const u64 inv25P  = pk2(inv25, inv25);

    for (int rr = 0; rr < IRS; rr += 5) {
        #pragma unroll
        for (int ph = 0; ph < 5; ++ph) {
            const int rrp = rr + ph;
            const int st  = rrp & (DEPTH - 1);

            // ---- wait for row rrp's copies, consume ----
            asm volatile("cp.async.wait_group 7;" ::: "memory");
            float4 xv = ring[wrp][st][lane];
            float4 yv = ring[wrp][st][32 + lane];

            // ---- refill same stage with row rrp+DEPTH ----
            {
                const int row = r0 + rrp + DEPTH;
                const int rL  = row < H ? row : (H - 1);
                const uint32_t zf = ((rrp + DEPTH) < IRS && row < H) ? zfc : 0u;
                const uint32_t dst = sb + ((uint32_t)st << 10) + sll;
                cp16(dst,       xb + (long)rL * W + cc, zf);
                cp16(dst + 512, yb + (long)rL * W + cc, zf);
                asm volatile("cp.async.commit_group;" ::: "memory");
            }

            // ---- pack new row, vertical running 5-sums (packed) ----
            u64 xyn[4];
            xyn[0] = pk2(xv.x, yv.x); xyn[1] = pk2(xv.y, yv.y);
            xyn[2] = pk2(xv.z, yv.z); xyn[3] = pk2(xv.w, yv.w);
            #pragma unroll
            for (int i = 0; i < 4; ++i) {
                vsP[i] = addx2(vsP[i], fmax2(xyr[ph][i], neg1P, xyn[i]));
                xyr[ph][i] = xyn[i];
            }

            // ---- neighbor (lane+1) vertical sums via half-shuffles ----
            u64 nP[4];
            #pragma unroll
            for (int i = 0; i < 4; ++i) {
                float lo, hi;
                upk2(lo, hi, vsP[i]);
                nP[i] = pk2(__shfl_down_sync(0xffffffffu, lo, 1),
                            __shfl_down_sync(0xffffffffu, hi, 1));
            }

            // ---- horizontal 5-sums -> 5x5 box sums (balanced tree, depth 3) ----
            u64 bP[4];
            {
                u64 s01 = addx2(vsP[0], vsP[1]);
                u64 s23 = addx2(vsP[2], vsP[3]);
                u64 m01 = addx2(nP[0],  nP[1]);
                u64 m23 = addx2(nP[2],  nP[3]);
                bP[0] = addx2(addx2(s01,    s23), nP[0]);   // vs0..3 + n0
                bP[1] = addx2(addx2(vsP[1], s23), m01);     // vs1..3 + n0,n1
                bP[2] = addx2(addx2(s23,    m01), nP[2]);   // vs2,3 + n0..2
                bP[3] = addx2(addx2(vsP[3], m01), m23);     // vs3 + n0..3
            }

            // ---- center pixels: row rrp-2 (ring slot (ph+3)%5), col u+2 ----
            const int sc = (ph + 3) % 5;
            u64 cP[4];
            cP[0] = xyr[sc][2];
            cP[1] = xyr[sc][3];
            {
                float l0, h0, l1, h1;
                upk2(l0, h0, xyr[sc][0]);
                upk2(l1, h1, xyr[sc][1]);
                cP[2] = pk2(__shfl_down_sync(0xffffffffu, l0, 1),
                            __shfl_down_sync(0xffffffffu, h0, 1));
                cP[3] = pk2(__shfl_down_sync(0xffffffffu, l1, 1),
                            __shfl_down_sync(0xffffffffu, h1, 1));
            }

            // ---- pc = (cx - bx/25) * (cy - by/25) ----
            float pc[4];
            #pragma unroll
            for (int i = 0; i < 4; ++i) {
                u64 t = fmax2(bP[i], ninv25P, cP[i]);
                float lo, hi;
                upk2(lo, hi, t);
                pc[i] = lo * hi;
            }

            // ---- horizontal 5-sum of p (balanced tree, depth 3; NO warmup
            //      gate: early garbage cancels exactly via the hp ring) ----
            float np[4];
            #pragma unroll
            for (int i = 0; i < 4; ++i)
                np[i] = __shfl_down_sync(0xffffffffu, pc[i], 1);

            float hp0, hp1, hp2, hp3;
            {
                float q01 = pc[0] + pc[1];
                float q23 = pc[2] + pc[3];
                float r01 = np[0] + np[1];
                float r23 = np[2] + np[3];
                hp0 = (q01 + q23) + np[0];      // pc0..3 + np0
                hp1 = (pc[1] + q23) + r01;      // pc1..3 + np0,np1
                hp2 = (q23 + r01) + np[2];      // pc2,3 + np0..2
                hp3 = (pc[3] + r01) + r23;      // pc3 + np0..3
            }

            // ---- vertical running 5-sum of hp (packed) ----
            u64 hp01 = pk2(hp0, hp1);
            u64 hp23 = pk2(hp2, hp3);
            vhpP[0] = addx2(vhpP[0], fmax2(hprP[ph][0], neg1P, hp01)); hprP[ph][0] = hp01;
            vhpP[1] = addx2(vhpP[1], fmax2(hprP[ph][1], neg1P, hp23)); hprP[ph][1] = hp23;

            if (rrp >= 8) {
                const int orow = r0 + rrp - 8;
                if (outok && orow < OH) {
                    u64 o01 = mulx2(vhpP[0], inv25P);
                    u64 o23 = mulx2(vhpP[1], inv25P);
                    float o0, o1, o2, o3;
                    upk2(o0, o1, o01);
                    upk2(o2, o3, o23);
                    __stcs((float4*)(ob + (long)orow * OW + c0),
                           make_float4(o0, o1, o2, o3));
                }
            }
        }
    }
}

extern "C" void kernel_launch(void* const* d_in, const int* in_sizes, int n_in,
                              void* d_out, int out_size)
{
    (void)in_sizes; (void)n_in; (void)out_size;
    const float* x = (const float*)d_in[0];
    const float* y = (const float*)d_in[1];
    float* out = (float*)d_out;

    dim3 grid(NCS, NRS / 4, NB);   // 9 col strips x 16 row strips x 16 images
    cov_kernel<<<grid, 128>>>(x, y, out);
}